// round 11
// baseline (speedup 1.0000x reference)
#include <cuda_runtime.h>
#include <cuda_bf16.h>
#include <cstdint>

// Problem constants (from reference): N=50000, F=128, E=800000, C=2
#define NMAX 50000

// Scratch projections: pu[n] = x[n] @ W_edge[:, :F].T  (4 floats)
//                      pv[n] = x[n] @ W_edge[:, F:].T  (4 floats)
__device__ float4 g_pu[NMAX];
__device__ float4 g_pv[NMAX];

// ---------------------------------------------------------------------------
// Kernel 1: one warp per node. Single coalesced read of x[n] (128 floats),
// 10 dot products (2 node potentials + 8 edge projections), warp reduce.
// ---------------------------------------------------------------------------
__global__ void crf_node_proj_kernel(const float* __restrict__ x,
                                     const float* __restrict__ W_node,
                                     const float* __restrict__ b_node,
                                     const float* __restrict__ W_edge,
                                     float* __restrict__ node_out,
                                     int N) {
    // sW rows: 0-1 = W_node[2][128]
    //          2-5 = W_edge[c][0:128]   (pu weights)
    //          6-9 = W_edge[c][128:256] (pv weights)
    __shared__ float4 sW[10][32];
    __shared__ float  sb[2];

    int tid = threadIdx.x;
    for (int i = tid; i < 320; i += blockDim.x) {
        int r = i >> 5, l = i & 31;
        float4 w;
        if (r < 2)       w = reinterpret_cast<const float4*>(W_node)[r * 32 + l];
        else if (r < 6)  w = reinterpret_cast<const float4*>(W_edge)[(r - 2) * 64 + l];
        else             w = reinterpret_cast<const float4*>(W_edge)[(r - 6) * 64 + 32 + l];
        sW[r][l] = w;
    }
    if (tid < 2) sb[tid] = b_node[tid];
    __syncthreads();

    int lane = tid & 31;
    int warp = tid >> 5;
    int wpb  = blockDim.x >> 5;

    for (int n = blockIdx.x * wpb + warp; n < N; n += gridDim.x * wpb) {
        float4 xv = reinterpret_cast<const float4*>(x)[n * 32 + lane];
        float acc[10];
#pragma unroll
        for (int r = 0; r < 10; r++) {
            float4 w = sW[r][lane];
            acc[r] = xv.x * w.x + xv.y * w.y + xv.z * w.z + xv.w * w.w;
        }
#pragma unroll
        for (int r = 0; r < 10; r++) {
#pragma unroll
            for (int off = 16; off > 0; off >>= 1)
                acc[r] += __shfl_xor_sync(0xffffffffu, acc[r], off);
        }
        if (lane == 0) {
            node_out[n * 2 + 0] = acc[0] + sb[0];
            node_out[n * 2 + 1] = acc[1] + sb[1];
            g_pu[n] = make_float4(acc[2], acc[3], acc[4], acc[5]);
            g_pv[n] = make_float4(acc[6], acc[7], acc[8], acc[9]);
        }
    }
}

// ---------------------------------------------------------------------------
// Kernel 2: one thread per edge. edge_index is INT32 (JAX downcasts int64
// without x64 mode). Two random float4 gathers from the 1.6 MB L2-resident
// projection tables, one coalesced float4 store.
// ---------------------------------------------------------------------------
__global__ void crf_edge_kernel(const int* __restrict__ ei,
                                const float* __restrict__ b_edge,
                                float* __restrict__ edge_out,
                                int E) {
    int e = blockIdx.x * blockDim.x + threadIdx.x;
    if (e >= E) return;
    float4 be = *reinterpret_cast<const float4*>(b_edge);
    int src = __ldg(&ei[e]);
    int dst = __ldg(&ei[E + e]);
    float4 a = g_pu[src];
    float4 b = g_pv[dst];
    reinterpret_cast<float4*>(edge_out)[e] =
        make_float4(a.x + b.x + be.x, a.y + b.y + be.y,
                    a.z + b.z + be.z, a.w + b.w + be.w);
}

// ---------------------------------------------------------------------------
// Launch
// ---------------------------------------------------------------------------
extern "C" void kernel_launch(void* const* d_in, const int* in_sizes, int n_in,
                              void* d_out, int out_size) {
    const float* x      = (const float*)d_in[0];  // [N, 128]
    const int*   ei     = (const int*)d_in[1];    // [2, E] int32 (JAX no-x64)
    const float* W_node = (const float*)d_in[2];  // [2, 128]
    const float* b_node = (const float*)d_in[3];  // [2]
    const float* W_edge = (const float*)d_in[4];  // [4, 256]
    const float* b_edge = (const float*)d_in[5];  // [4]

    int N = in_sizes[0] / 128;
    int E = in_sizes[1] / 2;

    float* node_out = (float*)d_out;           // [N, 2]
    float* edge_out = (float*)d_out + N * 2;   // [E, 4], 16B-aligned

    // Kernel 1: 256 threads = 8 warps/block, one warp per node
    int wpb = 8;
    int grid1 = (N + wpb - 1) / wpb;
    crf_node_proj_kernel<<<grid1, 256>>>(x, W_node, b_node, W_edge, node_out, N);

    // Kernel 2: one thread per edge
    int grid2 = (E + 255) / 256;
    crf_edge_kernel<<<grid2, 256>>>(ei, b_edge, edge_out, E);
}

// round 16
// speedup vs baseline: 1.1729x; 1.1729x over previous
#include <cuda_runtime.h>
#include <cuda_bf16.h>
#include <cstdint>

// Problem constants: N=50000, F=128, E=800000, C=2
#define NMAX 50000

// Scratch projections: pu[n] = x[n] @ W_edge[:, :F].T  (4 floats)
//                      pv[n] = x[n] @ W_edge[:, F:].T  (4 floats)
__device__ float4 g_pu[NMAX];
__device__ float4 g_pv[NMAX];

// ---------------------------------------------------------------------------
// Kernel 1: FOUR threads per node. Each thread owns a 32-float quarter of
// x[n] (8x LDG.128, MLP=8), accumulates 10 dot-product partials against
// smem-resident weights, then a 2-step shfl_xor reduce over the 4-lane group.
// All 4 lanes end with all 10 totals -> direct per-quarter stores.
//
// Weight smem layout: sWq[q][r*8 + j] (float4), row-padded to 81 float4 per
// quarter so quarter q starts at bank offset (81*4*q)%32 = 4q -> the 4
// distinct LDS.128 addresses per instruction hit banks {0-3},{4-7},{8-11},
// {12-15}: conflict-free, 8-lane broadcast per address.
// ---------------------------------------------------------------------------
__global__ void crf_node_proj_kernel(const float* __restrict__ x,
                                     const float* __restrict__ W_node,
                                     const float* __restrict__ b_node,
                                     const float* __restrict__ W_edge,
                                     float* __restrict__ node_out,
                                     int N) {
    __shared__ float4 sWq[4][81];   // [quarter][row*8 + j], rows 0-9
    __shared__ float  sb[2];

    const float4* Wn4 = reinterpret_cast<const float4*>(W_node);  // [2][32]
    const float4* We4 = reinterpret_cast<const float4*>(W_edge);  // [4][64]

    int tid = threadIdx.x;
    for (int i = tid; i < 320; i += blockDim.x) {
        int q = i / 80;
        int rem = i % 80;
        int r = rem / 8;
        int j = rem % 8;
        int k4 = q * 8 + j;           // float4 column 0..31 (128 floats)
        float4 w;
        if (r < 2)      w = Wn4[r * 32 + k4];
        else if (r < 6) w = We4[(r - 2) * 64 + k4];        // pu weights
        else            w = We4[(r - 6) * 64 + 32 + k4];   // pv weights
        sWq[q][r * 8 + j] = w;
    }
    if (tid < 2) sb[tid] = b_node[tid];
    __syncthreads();

    const float4* x4 = reinterpret_cast<const float4*>(x);
    float2* nout2 = reinterpret_cast<float2*>(node_out);

    int g      = blockIdx.x * blockDim.x + threadIdx.x;
    int stride = gridDim.x * blockDim.x;        // multiple of 4

    for (int base = g; (base >> 2) < N; base += stride) {
        int n = base >> 2;
        int q = base & 3;

        const float4* xr = x4 + n * 32 + q * 8;
        const float4* wr = sWq[q];

        float a0 = 0.f, a1 = 0.f, a2 = 0.f, a3 = 0.f, a4 = 0.f;
        float a5 = 0.f, a6 = 0.f, a7 = 0.f, a8 = 0.f, a9 = 0.f;

#pragma unroll
        for (int j = 0; j < 8; j++) {
            float4 xv = xr[j];
#pragma unroll
            for (int r = 0; r < 10; r++) {
                float4 w = wr[r * 8 + j];
                float d = xv.x * w.x + xv.y * w.y + xv.z * w.z + xv.w * w.w;
                switch (r) {
                    case 0: a0 += d; break; case 1: a1 += d; break;
                    case 2: a2 += d; break; case 3: a3 += d; break;
                    case 4: a4 += d; break; case 5: a5 += d; break;
                    case 6: a6 += d; break; case 7: a7 += d; break;
                    case 8: a8 += d; break; case 9: a9 += d; break;
                }
            }
        }

        // Reduce across the 4-lane group (lanes 4n..4n+3 are contiguous).
#pragma unroll
        for (int off = 1; off <= 2; off <<= 1) {
            a0 += __shfl_xor_sync(0xffffffffu, a0, off);
            a1 += __shfl_xor_sync(0xffffffffu, a1, off);
            a2 += __shfl_xor_sync(0xffffffffu, a2, off);
            a3 += __shfl_xor_sync(0xffffffffu, a3, off);
            a4 += __shfl_xor_sync(0xffffffffu, a4, off);
            a5 += __shfl_xor_sync(0xffffffffu, a5, off);
            a6 += __shfl_xor_sync(0xffffffffu, a6, off);
            a7 += __shfl_xor_sync(0xffffffffu, a7, off);
            a8 += __shfl_xor_sync(0xffffffffu, a8, off);
            a9 += __shfl_xor_sync(0xffffffffu, a9, off);
        }

        if (q == 0)      nout2[n] = make_float2(a0 + sb[0], a1 + sb[1]);
        else if (q == 1) g_pu[n]  = make_float4(a2, a3, a4, a5);
        else if (q == 2) g_pv[n]  = make_float4(a6, a7, a8, a9);
    }
}

// ---------------------------------------------------------------------------
// Kernel 2: FOUR edges per thread (block-strided so index loads and output
// stores stay perfectly coalesced). 8 independent float4 gathers in flight
// from the 1.6 MB L2-resident projection tables.
// ---------------------------------------------------------------------------
__global__ void crf_edge_kernel(const int* __restrict__ ei,
                                const float* __restrict__ b_edge,
                                float* __restrict__ edge_out,
                                int E) {
    int base = blockIdx.x * (blockDim.x * 4) + threadIdx.x;
    float4 be = *reinterpret_cast<const float4*>(b_edge);
    float4* out4 = reinterpret_cast<float4*>(edge_out);

    int e[4];
    int s[4], d[4];
    bool ok[4];
#pragma unroll
    for (int k = 0; k < 4; k++) {
        e[k] = base + k * blockDim.x;
        ok[k] = (e[k] < E);
        s[k] = ok[k] ? __ldg(&ei[e[k]]) : 0;
        d[k] = ok[k] ? __ldg(&ei[E + e[k]]) : 0;
    }

    float4 a[4], b[4];
#pragma unroll
    for (int k = 0; k < 4; k++) a[k] = g_pu[s[k]];
#pragma unroll
    for (int k = 0; k < 4; k++) b[k] = g_pv[d[k]];

#pragma unroll
    for (int k = 0; k < 4; k++) {
        if (ok[k]) {
            out4[e[k]] = make_float4(a[k].x + b[k].x + be.x,
                                     a[k].y + b[k].y + be.y,
                                     a[k].z + b[k].z + be.z,
                                     a[k].w + b[k].w + be.w);
        }
    }
}

// ---------------------------------------------------------------------------
// Launch
// ---------------------------------------------------------------------------
extern "C" void kernel_launch(void* const* d_in, const int* in_sizes, int n_in,
                              void* d_out, int out_size) {
    const float* x      = (const float*)d_in[0];  // [N, 128]
    const int*   ei     = (const int*)d_in[1];    // [2, E] int32
    const float* W_node = (const float*)d_in[2];  // [2, 128]
    const float* b_node = (const float*)d_in[3];  // [2]
    const float* W_edge = (const float*)d_in[4];  // [4, 256]
    const float* b_edge = (const float*)d_in[5];  // [4]

    int N = in_sizes[0] / 128;
    int E = in_sizes[1] / 2;

    float* node_out = (float*)d_out;           // [N, 2]
    float* edge_out = (float*)d_out + N * 2;   // [E, 4], 16B-aligned

    // Kernel 1: grid-stride, 4 blocks/SM to amortize weight-load startup.
    crf_node_proj_kernel<<<592, 256>>>(x, W_node, b_node, W_edge, node_out, N);

    // Kernel 2: 4 edges per thread, block-strided.
    int grid2 = (E + 1023) / 1024;
    crf_edge_kernel<<<grid2, 256>>>(ei, b_edge, edge_out, E);
}

// round 17
// speedup vs baseline: 1.4725x; 1.2554x over previous
#include <cuda_runtime.h>
#include <cuda_bf16.h>
#include <cstdint>

// Problem constants: N=50000, F=128, E=800000, C=2
#define NMAX 50000

// Scratch projections: pu[n] = x[n] @ W_edge[:, :F].T  (4 floats)
//                      pv[n] = x[n] @ W_edge[:, F:].T  (4 floats)
__device__ float4 g_pu[NMAX];
__device__ float4 g_pv[NMAX];

// ---------------------------------------------------------------------------
// Kernel 1: FOUR threads per node, COLUMN-INTERLEAVED ownership.
// Thread (n, q) owns float4 columns {q, q+4, q+8, ..., q+28} of x[n].
// At inner step j the 4-lane group reads float4s [4j, 4j+4) = one contiguous
// 64 B run; the warp's 8 nodes each touch ONE 128 B line per LDG -> 8
// wavefronts/LDG (vs 32 with blocked quarters). 10 dot-product partials
// against smem weights, 2-step shfl_xor reduce over the 4-lane group.
//
// Weight smem: sWq[q][r*8+j] = W_row_r[float4 4j+q], rows padded to 81
// float4 so access bank-group = (q+j) mod 8 -> 4 distinct groups,
// conflict-free 8-lane broadcast.
// ---------------------------------------------------------------------------
__global__ void crf_node_proj_kernel(const float* __restrict__ x,
                                     const float* __restrict__ W_node,
                                     const float* __restrict__ b_node,
                                     const float* __restrict__ W_edge,
                                     float* __restrict__ node_out,
                                     int N) {
    __shared__ float4 sWq[4][81];   // [quarter][row*8 + j], rows 0-9
    __shared__ float  sb[2];

    const float4* Wn4 = reinterpret_cast<const float4*>(W_node);  // [2][32]
    const float4* We4 = reinterpret_cast<const float4*>(W_edge);  // [4][64]

    int tid = threadIdx.x;
    for (int i = tid; i < 320; i += blockDim.x) {
        int q = i / 80;
        int rem = i % 80;
        int r = rem / 8;
        int j = rem % 8;
        int k4 = j * 4 + q;           // interleaved float4 column 0..31
        float4 w;
        if (r < 2)      w = Wn4[r * 32 + k4];
        else if (r < 6) w = We4[(r - 2) * 64 + k4];        // pu weights
        else            w = We4[(r - 6) * 64 + 32 + k4];   // pv weights
        sWq[q][r * 8 + j] = w;
    }
    if (tid < 2) sb[tid] = b_node[tid];
    __syncthreads();

    const float4* x4 = reinterpret_cast<const float4*>(x);
    float2* nout2 = reinterpret_cast<float2*>(node_out);

    int g      = blockIdx.x * blockDim.x + threadIdx.x;
    int stride = gridDim.x * blockDim.x;        // multiple of 4

    for (int base = g; (base >> 2) < N; base += stride) {
        int n = base >> 2;
        int q = base & 3;

        const float4* xr = x4 + n * 32 + q;   // strided by 4 float4 per step
        const float4* wr = sWq[q];

        float a0 = 0.f, a1 = 0.f, a2 = 0.f, a3 = 0.f, a4 = 0.f;
        float a5 = 0.f, a6 = 0.f, a7 = 0.f, a8 = 0.f, a9 = 0.f;

#pragma unroll
        for (int j = 0; j < 8; j++) {
            float4 xv = xr[4 * j];
#pragma unroll
            for (int r = 0; r < 10; r++) {
                float4 w = wr[r * 8 + j];
                float d = xv.x * w.x + xv.y * w.y + xv.z * w.z + xv.w * w.w;
                switch (r) {
                    case 0: a0 += d; break; case 1: a1 += d; break;
                    case 2: a2 += d; break; case 3: a3 += d; break;
                    case 4: a4 += d; break; case 5: a5 += d; break;
                    case 6: a6 += d; break; case 7: a7 += d; break;
                    case 8: a8 += d; break; case 9: a9 += d; break;
                }
            }
        }

        // Reduce across the 4-lane group (lanes 4n..4n+3 are contiguous).
#pragma unroll
        for (int off = 1; off <= 2; off <<= 1) {
            a0 += __shfl_xor_sync(0xffffffffu, a0, off);
            a1 += __shfl_xor_sync(0xffffffffu, a1, off);
            a2 += __shfl_xor_sync(0xffffffffu, a2, off);
            a3 += __shfl_xor_sync(0xffffffffu, a3, off);
            a4 += __shfl_xor_sync(0xffffffffu, a4, off);
            a5 += __shfl_xor_sync(0xffffffffu, a5, off);
            a6 += __shfl_xor_sync(0xffffffffu, a6, off);
            a7 += __shfl_xor_sync(0xffffffffu, a7, off);
            a8 += __shfl_xor_sync(0xffffffffu, a8, off);
            a9 += __shfl_xor_sync(0xffffffffu, a9, off);
        }

        if (q == 0)      nout2[n] = make_float2(a0 + sb[0], a1 + sb[1]);
        else if (q == 1) g_pu[n]  = make_float4(a2, a3, a4, a5);
        else if (q == 2) g_pv[n]  = make_float4(a6, a7, a8, a9);
    }
}

// ---------------------------------------------------------------------------
// Kernel 2: FOUR edges per thread (block-strided; coalesced index loads and
// output stores). Gathers are at the L1 wavefront floor (~1 line per edge
// endpoint); unchanged.
// ---------------------------------------------------------------------------
__global__ void crf_edge_kernel(const int* __restrict__ ei,
                                const float* __restrict__ b_edge,
                                float* __restrict__ edge_out,
                                int E) {
    int base = blockIdx.x * (blockDim.x * 4) + threadIdx.x;
    float4 be = *reinterpret_cast<const float4*>(b_edge);
    float4* out4 = reinterpret_cast<float4*>(edge_out);

    int e[4];
    int s[4], d[4];
    bool ok[4];
#pragma unroll
    for (int k = 0; k < 4; k++) {
        e[k] = base + k * blockDim.x;
        ok[k] = (e[k] < E);
        s[k] = ok[k] ? __ldg(&ei[e[k]]) : 0;
        d[k] = ok[k] ? __ldg(&ei[E + e[k]]) : 0;
    }

    float4 a[4], b[4];
#pragma unroll
    for (int k = 0; k < 4; k++) a[k] = g_pu[s[k]];
#pragma unroll
    for (int k = 0; k < 4; k++) b[k] = g_pv[d[k]];

#pragma unroll
    for (int k = 0; k < 4; k++) {
        if (ok[k]) {
            out4[e[k]] = make_float4(a[k].x + b[k].x + be.x,
                                     a[k].y + b[k].y + be.y,
                                     a[k].z + b[k].z + be.z,
                                     a[k].w + b[k].w + be.w);
        }
    }
}

// ---------------------------------------------------------------------------
// Launch
// ---------------------------------------------------------------------------
extern "C" void kernel_launch(void* const* d_in, const int* in_sizes, int n_in,
                              void* d_out, int out_size) {
    const float* x      = (const float*)d_in[0];  // [N, 128]
    const int*   ei     = (const int*)d_in[1];    // [2, E] int32
    const float* W_node = (const float*)d_in[2];  // [2, 128]
    const float* b_node = (const float*)d_in[3];  // [2]
    const float* W_edge = (const float*)d_in[4];  // [4, 256]
    const float* b_edge = (const float*)d_in[5];  // [4]

    int N = in_sizes[0] / 128;
    int E = in_sizes[1] / 2;

    float* node_out = (float*)d_out;           // [N, 2]
    float* edge_out = (float*)d_out + N * 2;   // [E, 4], 16B-aligned

    // Kernel 1: ~one work-item (node-quarter) per thread.
    int items = N * 4;
    int grid1 = (items + 255) / 256;   // 782
    crf_node_proj_kernel<<<grid1, 256>>>(x, W_node, b_node, W_edge, node_out, N);

    // Kernel 2: 4 edges per thread, block-strided.
    int grid2 = (E + 1023) / 1024;
    crf_edge_kernel<<<grid2, 256>>>(ei, b_edge, edge_out, E);
}